// round 2
// baseline (speedup 1.0000x reference)
#include <cuda_runtime.h>
#include <math.h>

#define HID   4096
#define IH    8192
#define VOCAB 32000

// Scratch (allocation-free: __device__ globals)
__device__ float g_hnew[HID];
__device__ float g_logits[VOCAB];

__device__ __forceinline__ float dot4(float4 a, float4 b) {
    return a.x * b.x + a.y * b.y + a.z * b.z + a.w * b.w;
}

// ---------------------------------------------------------------------------
// Kernel 1: fused 4-gate GEMV + LSTM cell update.
// TWO hidden rows per block: 8 weight streams (evict-first) + 1 shared
// `combined` load per iteration. 2048 blocks x 256 threads.
// ---------------------------------------------------------------------------
__global__ __launch_bounds__(256) void lstm_gates_kernel(
    const float* __restrict__ x,  const float* __restrict__ h,
    const float* __restrict__ c,
    const float* __restrict__ Wf, const float* __restrict__ bf,
    const float* __restrict__ Wi, const float* __restrict__ bi,
    const float* __restrict__ Wo, const float* __restrict__ bo,
    const float* __restrict__ Wc, const float* __restrict__ bc,
    float* __restrict__ out_h, float* __restrict__ out_c)
{
    const int row0 = blockIdx.x * 2;
    const size_t off0 = (size_t)row0 * IH;

    const float4* __restrict__ wf0 = (const float4*)(Wf + off0);
    const float4* __restrict__ wi0 = (const float4*)(Wi + off0);
    const float4* __restrict__ wo0 = (const float4*)(Wo + off0);
    const float4* __restrict__ wc0 = (const float4*)(Wc + off0);
    const float4* __restrict__ wf1 = (const float4*)(Wf + off0 + IH);
    const float4* __restrict__ wi1 = (const float4*)(Wi + off0 + IH);
    const float4* __restrict__ wo1 = (const float4*)(Wo + off0 + IH);
    const float4* __restrict__ wc1 = (const float4*)(Wc + off0 + IH);
    const float4* __restrict__ x4 = (const float4*)x;
    const float4* __restrict__ h4 = (const float4*)h;

    // acc[0..3] = f,i,o,c for row0 ; acc[4..7] = f,i,o,c for row1
    float acc[8];
    #pragma unroll
    for (int k = 0; k < 8; k++) acc[k] = 0.f;

    // IH/4 = 2048 float4 positions; 256 threads -> 8 iterations
    #pragma unroll
    for (int j = threadIdx.x; j < IH / 4; j += 256) {
        float4 cb = (j < HID / 4) ? x4[j] : h4[j - HID / 4];
        float4 f0 = __ldcs(wf0 + j);
        float4 i0 = __ldcs(wi0 + j);
        float4 o0 = __ldcs(wo0 + j);
        float4 c0 = __ldcs(wc0 + j);
        float4 f1 = __ldcs(wf1 + j);
        float4 i1 = __ldcs(wi1 + j);
        float4 o1 = __ldcs(wo1 + j);
        float4 c1 = __ldcs(wc1 + j);
        acc[0] += dot4(f0, cb);
        acc[1] += dot4(i0, cb);
        acc[2] += dot4(o0, cb);
        acc[3] += dot4(c0, cb);
        acc[4] += dot4(f1, cb);
        acc[5] += dot4(i1, cb);
        acc[6] += dot4(o1, cb);
        acc[7] += dot4(c1, cb);
    }

    // warp reduce all 8 accumulators
    #pragma unroll
    for (int off = 16; off > 0; off >>= 1) {
        #pragma unroll
        for (int k = 0; k < 8; k++)
            acc[k] += __shfl_down_sync(0xffffffffu, acc[k], off);
    }

    __shared__ float red[8][8];   // [warp][acc]
    const int wid = threadIdx.x >> 5;
    const int lid = threadIdx.x & 31;
    if (lid == 0) {
        #pragma unroll
        for (int k = 0; k < 8; k++) red[wid][k] = acc[k];
    }
    __syncthreads();

    if (threadIdx.x < 2) {
        const int r = threadIdx.x;            // local row 0/1
        const int row = row0 + r;
        float tf = 0.f, ti = 0.f, to = 0.f, tc = 0.f;
        #pragma unroll
        for (int w = 0; w < 8; w++) {
            tf += red[w][r * 4 + 0];
            ti += red[w][r * 4 + 1];
            to += red[w][r * 4 + 2];
            tc += red[w][r * 4 + 3];
        }
        tf += bf[row]; ti += bi[row]; to += bo[row]; tc += bc[row];

        const float fg = 1.f / (1.f + expf(-tf));
        const float ig = 1.f / (1.f + expf(-ti));
        const float og = 1.f / (1.f + expf(-to));
        const float cc = tanhf(tc);

        const float cn = fg * c[row] + ig * cc;
        const float hn = og * tanhf(cn);

        out_c[row]  = cn;
        out_h[row]  = hn;
        g_hnew[row] = hn;
    }
}

// ---------------------------------------------------------------------------
// Kernel 2: output projection GEMV. EIGHT vocab rows per 256-thread block:
// one h load serves 8 weight streams. 4000 blocks.
// ---------------------------------------------------------------------------
__global__ __launch_bounds__(256) void gemv_out_kernel(
    const float* __restrict__ Wout, const float* __restrict__ bout)
{
    const int row0 = blockIdx.x * 8;
    const float4* __restrict__ w0 = (const float4*)(Wout + (size_t)row0 * HID);
    const float4* __restrict__ hv = (const float4*)g_hnew;
    const int stride4 = HID / 4;   // 1024 float4 per row

    float acc[8];
    #pragma unroll
    for (int k = 0; k < 8; k++) acc[k] = 0.f;

    // 1024 positions, 256 threads -> 4 iterations
    #pragma unroll
    for (int j = threadIdx.x; j < stride4; j += 256) {
        float4 hb = hv[j];
        #pragma unroll
        for (int k = 0; k < 8; k++) {
            float4 a = __ldcs(w0 + (size_t)k * stride4 + j);
            acc[k] += dot4(a, hb);
        }
    }

    #pragma unroll
    for (int off = 16; off > 0; off >>= 1) {
        #pragma unroll
        for (int k = 0; k < 8; k++)
            acc[k] += __shfl_down_sync(0xffffffffu, acc[k], off);
    }

    __shared__ float red[8][8];   // [warp][row]
    const int wid = threadIdx.x >> 5;
    const int lid = threadIdx.x & 31;
    if (lid == 0) {
        #pragma unroll
        for (int k = 0; k < 8; k++) red[wid][k] = acc[k];
    }
    __syncthreads();

    if (threadIdx.x < 8) {
        const int r = threadIdx.x;
        float s = 0.f;
        #pragma unroll
        for (int w = 0; w < 8; w++) s += red[w][r];
        g_logits[row0 + r] = s + bout[row0 + r];
    }
}

// ---------------------------------------------------------------------------
// Kernel 3: log_softmax over 32000 logits. Single block, online max+sumexp
// (2 passes total instead of 3).
// ---------------------------------------------------------------------------
__global__ __launch_bounds__(1024) void log_softmax_kernel(float* __restrict__ out)
{
    __shared__ float red_m[32], red_s[32];
    __shared__ float s_lse;
    const int tid = threadIdx.x;
    const int wid = tid >> 5;
    const int lid = tid & 31;

    // Pass 1: online (max, sumexp)
    float m = -INFINITY, s = 0.f;
    for (int i = tid; i < VOCAB; i += 1024) {
        float v = g_logits[i];
        float mn = fmaxf(m, v);
        s = s * expf(m - mn) + expf(v - mn);
        m = mn;
    }
    #pragma unroll
    for (int off = 16; off > 0; off >>= 1) {
        float mo = __shfl_down_sync(0xffffffffu, m, off);
        float so = __shfl_down_sync(0xffffffffu, s, off);
        float mn = fmaxf(m, mo);
        s = s * expf(m - mn) + so * expf(mo - mn);
        m = mn;
    }
    if (lid == 0) { red_m[wid] = m; red_s[wid] = s; }
    __syncthreads();
    if (tid == 0) {
        float mm = red_m[0], ss = red_s[0];
        #pragma unroll
        for (int w = 1; w < 32; w++) {
            float mn = fmaxf(mm, red_m[w]);
            ss = ss * expf(mm - mn) + red_s[w] * expf(red_m[w] - mn);
            mm = mn;
        }
        s_lse = mm + logf(ss);
    }
    __syncthreads();
    const float lse = s_lse;

    // Pass 2: write result
    for (int i = tid; i < VOCAB; i += 1024) out[i] = g_logits[i] - lse;
}

// ---------------------------------------------------------------------------
// d_in order (metadata): x, h, c, W_f, b_f, W_i, b_i, W_o, b_o, W_c, b_c,
//                        W_out, b_out
// d_out layout: [logits 32000][h_new 4096][c_new 4096]
// ---------------------------------------------------------------------------
extern "C" void kernel_launch(void* const* d_in, const int* in_sizes, int n_in,
                              void* d_out, int out_size)
{
    const float* x    = (const float*)d_in[0];
    const float* h    = (const float*)d_in[1];
    const float* c    = (const float*)d_in[2];
    const float* Wf   = (const float*)d_in[3];
    const float* bf   = (const float*)d_in[4];
    const float* Wi   = (const float*)d_in[5];
    const float* bi   = (const float*)d_in[6];
    const float* Wo   = (const float*)d_in[7];
    const float* bo   = (const float*)d_in[8];
    const float* Wc   = (const float*)d_in[9];
    const float* bc   = (const float*)d_in[10];
    const float* Wout = (const float*)d_in[11];
    const float* bout = (const float*)d_in[12];

    float* out = (float*)d_out;
    float* out_h = out + VOCAB;         // 32000..36095
    float* out_c = out + VOCAB + HID;   // 36096..40191

    lstm_gates_kernel<<<HID / 2, 256>>>(x, h, c, Wf, bf, Wi, bi, Wo, bo,
                                        Wc, bc, out_h, out_c);
    gemv_out_kernel<<<VOCAB / 8, 256>>>(Wout, bout);
    log_softmax_kernel<<<1, 1024>>>(out);
}

// round 3
// speedup vs baseline: 1.0344x; 1.0344x over previous
#include <cuda_runtime.h>
#include <math.h>

#define HID   4096
#define IH    8192
#define VOCAB 32000

// Scratch (allocation-free: __device__ globals)
__device__ float g_gates[4 * HID];   // [gate][row]: f,i,o,c pre-activations
__device__ float g_hnew[HID];
__device__ float g_logits[VOCAB];

__device__ __forceinline__ float dot4(float4 a, float4 b) {
    return a.x * b.x + a.y * b.y + a.z * b.z + a.w * b.w;
}

// ---------------------------------------------------------------------------
// Kernel 1: gate GEMV. One (gate,row) pair per 128-thread CTA -> 16384 CTAs,
// each streaming one contiguous 32KB weight row (mirrors the pattern that
// measured ~6.9 TB/s on the output projection).
// ---------------------------------------------------------------------------
__global__ __launch_bounds__(128) void gate_gemv_kernel(
    const float* __restrict__ x,  const float* __restrict__ h,
    const float* __restrict__ Wf, const float* __restrict__ Wi,
    const float* __restrict__ Wo, const float* __restrict__ Wc)
{
    const int gate = blockIdx.x >> 12;          // 0..3
    const int row  = blockIdx.x & (HID - 1);    // 0..4095

    const float* W = (gate == 0) ? Wf : (gate == 1) ? Wi
                    : (gate == 2) ? Wo : Wc;
    const float4* __restrict__ w  = (const float4*)(W + (size_t)row * IH);
    const float4* __restrict__ x4 = (const float4*)x;
    const float4* __restrict__ h4 = (const float4*)h;

    float s = 0.f;
    // IH/4 = 2048 float4 positions; 128 threads -> 16 iterations
    for (int j = threadIdx.x; j < IH / 4; j += 128) {
        float4 cb = (j < HID / 4) ? x4[j] : h4[j - HID / 4];
        s += dot4(w[j], cb);
    }

    #pragma unroll
    for (int off = 16; off > 0; off >>= 1)
        s += __shfl_down_sync(0xffffffffu, s, off);

    __shared__ float red[4];
    const int wid = threadIdx.x >> 5;
    const int lid = threadIdx.x & 31;
    if (lid == 0) red[wid] = s;
    __syncthreads();

    if (threadIdx.x == 0)
        g_gates[gate * HID + row] = red[0] + red[1] + red[2] + red[3];
}

// ---------------------------------------------------------------------------
// Kernel 2: LSTM cell combine (nonlinearities + state update). Tiny.
// ---------------------------------------------------------------------------
__global__ __launch_bounds__(256) void lstm_combine_kernel(
    const float* __restrict__ c,
    const float* __restrict__ bf, const float* __restrict__ bi,
    const float* __restrict__ bo, const float* __restrict__ bc,
    float* __restrict__ out_h, float* __restrict__ out_c)
{
    const int row = blockIdx.x * 256 + threadIdx.x;
    if (row >= HID) return;

    const float tf = g_gates[0 * HID + row] + bf[row];
    const float ti = g_gates[1 * HID + row] + bi[row];
    const float to = g_gates[2 * HID + row] + bo[row];
    const float tc = g_gates[3 * HID + row] + bc[row];

    const float fg = 1.f / (1.f + expf(-tf));
    const float ig = 1.f / (1.f + expf(-ti));
    const float og = 1.f / (1.f + expf(-to));
    const float cc = tanhf(tc);

    const float cn = fg * c[row] + ig * cc;
    const float hn = og * tanhf(cn);

    out_c[row]  = cn;
    out_h[row]  = hn;
    g_hnew[row] = hn;
}

// ---------------------------------------------------------------------------
// Kernel 3: output projection GEMV. One 128-thread CTA per vocab row
// (R1 version: measured ~6.9 TB/s).
// ---------------------------------------------------------------------------
__global__ __launch_bounds__(128) void gemv_out_kernel(
    const float* __restrict__ Wout, const float* __restrict__ bout)
{
    const int row = blockIdx.x;
    const float4* __restrict__ w = (const float4*)(Wout + (size_t)row * HID);
    const float4* __restrict__ hv = (const float4*)g_hnew;

    float s = 0.f;
    // HID/4 = 1024 float4s; 128 threads -> 8 iterations
    #pragma unroll
    for (int j = threadIdx.x; j < HID / 4; j += 128) {
        s += dot4(w[j], hv[j]);
    }

    #pragma unroll
    for (int off = 16; off > 0; off >>= 1)
        s += __shfl_down_sync(0xffffffffu, s, off);

    __shared__ float red[4];
    const int wid = threadIdx.x >> 5;
    const int lid = threadIdx.x & 31;
    if (lid == 0) red[wid] = s;
    __syncthreads();

    if (threadIdx.x == 0)
        g_logits[row] = red[0] + red[1] + red[2] + red[3] + bout[row];
}

// ---------------------------------------------------------------------------
// Kernel 4: log_softmax over 32000 logits. Single block, online max+sumexp.
// ---------------------------------------------------------------------------
__global__ __launch_bounds__(1024) void log_softmax_kernel(float* __restrict__ out)
{
    __shared__ float red_m[32], red_s[32];
    __shared__ float s_lse;
    const int tid = threadIdx.x;
    const int wid = tid >> 5;
    const int lid = tid & 31;

    float m = -INFINITY, s = 0.f;
    for (int i = tid; i < VOCAB; i += 1024) {
        float v = g_logits[i];
        float mn = fmaxf(m, v);
        s = s * expf(m - mn) + expf(v - mn);
        m = mn;
    }
    #pragma unroll
    for (int off = 16; off > 0; off >>= 1) {
        float mo = __shfl_down_sync(0xffffffffu, m, off);
        float so = __shfl_down_sync(0xffffffffu, s, off);
        float mn = fmaxf(m, mo);
        s = s * expf(m - mn) + so * expf(mo - mn);
        m = mn;
    }
    if (lid == 0) { red_m[wid] = m; red_s[wid] = s; }
    __syncthreads();
    if (tid == 0) {
        float mm = red_m[0], ss = red_s[0];
        #pragma unroll
        for (int w = 1; w < 32; w++) {
            float mn = fmaxf(mm, red_m[w]);
            ss = ss * expf(mm - mn) + red_s[w] * expf(red_m[w] - mn);
            mm = mn;
        }
        s_lse = mm + logf(ss);
    }
    __syncthreads();
    const float lse = s_lse;

    for (int i = tid; i < VOCAB; i += 1024) out[i] = g_logits[i] - lse;
}

// ---------------------------------------------------------------------------
// d_in order (metadata): x, h, c, W_f, b_f, W_i, b_i, W_o, b_o, W_c, b_c,
//                        W_out, b_out
// d_out layout: [logits 32000][h_new 4096][c_new 4096]
// ---------------------------------------------------------------------------
extern "C" void kernel_launch(void* const* d_in, const int* in_sizes, int n_in,
                              void* d_out, int out_size)
{
    const float* x    = (const float*)d_in[0];
    const float* h    = (const float*)d_in[1];
    const float* c    = (const float*)d_in[2];
    const float* Wf   = (const float*)d_in[3];
    const float* bf   = (const float*)d_in[4];
    const float* Wi   = (const float*)d_in[5];
    const float* bi   = (const float*)d_in[6];
    const float* Wo   = (const float*)d_in[7];
    const float* bo   = (const float*)d_in[8];
    const float* Wc   = (const float*)d_in[9];
    const float* bc   = (const float*)d_in[10];
    const float* Wout = (const float*)d_in[11];
    const float* bout = (const float*)d_in[12];

    float* out = (float*)d_out;
    float* out_h = out + VOCAB;         // 32000..36095
    float* out_c = out + VOCAB + HID;   // 36096..40191

    gate_gemv_kernel<<<4 * HID, 128>>>(x, h, Wf, Wi, Wo, Wc);
    lstm_combine_kernel<<<HID / 256, 256>>>(c, bf, bi, bo, bc, out_h, out_c);
    gemv_out_kernel<<<VOCAB, 128>>>(Wout, bout);
    log_softmax_kernel<<<1, 1024>>>(out);
}